// round 16
// baseline (speedup 1.0000x reference)
#include <cuda_runtime.h>
#include <cstdint>

#define BATCH   64
#define NV      68
#define MC      46
#define ZL      384
#define NE      368
#define NITERS  5
#define MAXDEG  16
#define MAXVDEG 32
#define LLRCLIP 20.0f

// ---------------- device scratch (no cudaMalloc allowed) ----------------
__device__ __align__(16) int8_t g_c2v[BATCH * NE * ZL]; // messages, CN-domain, 2*llr
__device__ float  g_tot[BATCH * NV * ZL];               // total belief, [B][N][Z]
__device__ int2   g_meta[MC * MAXDEG];                  // .x=(vn*ZL)<<9|shift, .y=e*ZL
__device__ int    g_cn_deg[MC];
__device__ int2   g_vmeta[NV * MAXVDEG];                // .x=e*ZL, .y=shift
__device__ int    g_vn_deg[NV];

// ---------------- build edge metadata (parallel; list order irrelevant:
// min-sum mins, sign-xor and integer sums are order-independent) ---------
__global__ void setup_kernel(const int* __restrict__ edge_cn,
                             const int* __restrict__ edge_vn,
                             const int* __restrict__ edge_shift) {
    __shared__ int ccnt[MC], vcnt[NV];
    int t = threadIdx.x;
    if (t < MC) ccnt[t] = 0;
    if (t < NV) vcnt[t] = 0;
    __syncthreads();
    if (t < NE) {
        int m = edge_cn[t], n = edge_vn[t], sh = edge_shift[t];
        int slot = atomicAdd(&ccnt[m], 1);
        if (slot < MAXDEG) {
            int2 md; md.x = ((n * ZL) << 9) | (sh & 511); md.y = t * ZL;
            g_meta[m * MAXDEG + slot] = md;
        }
        int vslot = atomicAdd(&vcnt[n], 1);
        if (vslot < MAXVDEG) {
            int2 vm; vm.x = t * ZL; vm.y = sh;
            g_vmeta[n * MAXVDEG + vslot] = vm;
        }
    }
    __syncthreads();
    if (t < MC) g_cn_deg[t] = min(ccnt[t], MAXDEG);
    if (t < NV) g_vn_deg[t] = min(vcnt[t], MAXVDEG);
}

__device__ __forceinline__ float sext_byte(unsigned w, int j) {
    return (float)((int)(w << ((3 - j) * 8)) >> 24);
}

// ---------------- CN update: 4z-vectorized min-sum + quantize -----------
// grid (MC, BATCH/4), block 384 = 4 batch-groups x 96 threads.
// Thread handles 4 consecutive zc: c2v as one word load/store per edge,
// tot as two coalesced float4 loads + warp-uniform select per edge.
template<bool FIRST>
__global__ __launch_bounds__(384) void cn_kernel(
    const float* __restrict__ xa,
    const float* __restrict__ cn_weight,
    int it)
{
    const int m   = blockIdx.x;
    const int g   = threadIdx.x / 96;            // batch sub-group
    const int r   = threadIdx.x % 96;
    const int b   = blockIdx.y * 4 + g;
    const int zc0 = r * 4;

    __shared__ int2 s_md[MAXDEG];
    __shared__ int  s_degs;
    if (threadIdx.x == 0) s_degs = g_cn_deg[m];
    if (threadIdx.x < MAXDEG) s_md[threadIdx.x] = g_meta[m * MAXDEG + threadIdx.x];
    __syncthreads();

    const int deg = s_degs;
    const float w = cn_weight[it];
    const float* __restrict__ totb = (FIRST ? xa : g_tot) + (size_t)b * NV * ZL;
    int8_t*      __restrict__ c2vb = g_c2v + (size_t)b * NE * ZL;

    if (deg == 8) {
        unsigned cw[8];
        float4   tv[8];                 // selected tot values t0..t3 per edge
        int      widx[8];

        // ---------- pass 1: loads + per-z min/sign tracking ----------
        #pragma unroll
        for (int k = 0; k < 8; k++) {
            int2 e = s_md[k];
            int sh = e.x & 511, rb = e.x >> 9;
            widx[k] = e.y + zc0;
            if (!FIRST) cw[k] = *(const unsigned*)(c2vb + widx[k]);
            else        cw[k] = 0;
            int z0 = zc0 - sh; z0 += (z0 >> 31) & ZL;  // (zc0 - sh) mod ZL
            int o  = z0 & 3;                            // warp-uniform
            int a0 = z0 - o;
            int a1 = a0 + 4; if (a1 >= ZL) a1 -= ZL;
            float4 fa = *(const float4*)(totb + rb + a0);
            float4 fb = *(const float4*)(totb + rb + a1);
            float4 t;
            switch (o) {                                // uniform, no divergence
                case 0:  t.x=fa.x; t.y=fa.y; t.z=fa.z; t.w=fa.w; break;
                case 1:  t.x=fa.y; t.y=fa.z; t.z=fa.w; t.w=fb.x; break;
                case 2:  t.x=fa.z; t.y=fa.w; t.z=fb.x; t.w=fb.y; break;
                default: t.x=fa.w; t.y=fb.x; t.z=fb.y; t.w=fb.z; break;
            }
            tv[k] = t;
        }

        float m1[4] = {1e9f,1e9f,1e9f,1e9f};
        float m2[4] = {1e9f,1e9f,1e9f,1e9f};
        int   sgn[4] = {0,0,0,0};
        #pragma unroll
        for (int k = 0; k < 8; k++) {
            #pragma unroll
            for (int j = 0; j < 4; j++) {
                float t = (j==0)?tv[k].x:(j==1)?tv[k].y:(j==2)?tv[k].z:tv[k].w;
                float c = FIRST ? 0.0f : 0.5f * sext_byte(cw[k], j);
                float v = fminf(fmaxf(t - c, -LLRCLIP), LLRCLIP);
                if (v < 0.0f) sgn[j] ^= 1;
                float mag = fabsf(v);
                if (mag < m1[j])      { m2[j] = m1[j]; m1[j] = mag; }
                else if (mag > m1[j]) { m2[j] = fminf(m2[j], mag); }
            }
        }

        // per-z quantized magnitudes (q odd-symmetric: sign factors out)
        int i1[4], i2[4];
        #pragma unroll
        for (int j = 0; j < 4; j++) {
            i1[j] = (int)fminf(fmaxf(rintf(2.0f * w * m1[j]), -15.0f), 15.0f);
            i2[j] = (int)fminf(fmaxf(rintf(2.0f * w * m2[j]), -15.0f), 15.0f);
        }

        // ---------- pass 2: recompute v from regs, assemble words ----------
        #pragma unroll
        for (int k = 0; k < 8; k++) {
            unsigned ow = 0;
            #pragma unroll
            for (int j = 0; j < 4; j++) {
                float t = (j==0)?tv[k].x:(j==1)?tv[k].y:(j==2)?tv[k].z:tv[k].w;
                float c = FIRST ? 0.0f : 0.5f * sext_byte(cw[k], j);
                float v = fminf(fmaxf(t - c, -LLRCLIP), LLRCLIP);
                bool useb = (fabsf(v) == m1[j]);     // ties on min1 get min2
                bool s    = (v < 0.0f) ^ (sgn[j] != 0);
                int  qi   = useb ? i2[j] : i1[j];
                int  qv   = s ? -qi : qi;
                ow |= (unsigned)(qv & 0xff) << (8 * j);
            }
            *(unsigned*)(c2vb + widx[k]) = ow;
        }
    } else {
        // generic scalar fallback over the 4 zc (dataset uses deg==8)
        for (int j = 0; j < 4; j++) {
            int zc = zc0 + j;
            float m1 = 1e9f, m2 = 1e9f;
            int sgn = 0;
            for (int k = 0; k < deg; k++) {
                int2 e = s_md[k];
                int z = zc - (e.x & 511); z += (z >> 31) & ZL;
                float c = FIRST ? 0.0f : 0.5f * (float)c2vb[e.y + zc];
                float v = fminf(fmaxf(totb[(e.x >> 9) + z] - c, -LLRCLIP), LLRCLIP);
                if (v < 0.0f) sgn ^= 1;
                float mag = fabsf(v);
                if (mag < m1)      { m2 = m1; m1 = mag; }
                else if (mag > m1) { m2 = fminf(m2, mag); }
            }
            for (int k = 0; k < deg; k++) {
                int2 e = s_md[k];
                int z = zc - (e.x & 511); z += (z >> 31) & ZL;
                float c = FIRST ? 0.0f : 0.5f * (float)c2vb[e.y + zc];
                float v = fminf(fmaxf(totb[(e.x >> 9) + z] - c, -LLRCLIP), LLRCLIP);
                float mag  = fabsf(v);
                float emin = (mag == m1) ? m2 : m1;
                bool flip  = (v < 0.0f) ^ (sgn != 0);
                float x    = (flip ? -w : w) * emin;
                float q2   = fminf(fmaxf(rintf(x + x), -15.0f), 15.0f);
                c2vb[e.y + zc] = (int8_t)q2;
            }
        }
    }
}

// ---------------- VN update: 4z-vectorized gather via funnel shift ------
// grid (ZL/32, BATCH), block 256 = 8 z-groups(4z) x 32 n-groups.
// Integer-exact accumulation -> *0.5 -> +xa matches segment_sum bitwise.
#define VZC 32
__global__ __launch_bounds__(256) void vn_kernel(
    const float* __restrict__ xa,
    float*       __restrict__ out,     // slab for this iter: [B][ZL][NV]
    int write_tot)
{
    __shared__ float tile[NV][VZC + 1];

    const int b  = blockIdx.y;
    const int z0 = blockIdx.x * VZC;
    const int zg = threadIdx.x & 7;        // 8 groups of 4 z
    const int ng = threadIdx.x >> 3;       // 0..31
    const int zl = zg * 4;
    const int z  = z0 + zl;

    const size_t base = (size_t)b * NV * ZL;
    const float* __restrict__ xab  = xa    + base;
    float*       __restrict__ totb = g_tot + base;
    const int8_t* __restrict__ c2vb = g_c2v + (size_t)b * NE * ZL;

    for (int n = ng; n < NV; n += 32) {
        int d = g_vn_deg[n];
        const int2* __restrict__ vm = &g_vmeta[n * MAXVDEG];
        int s0 = 0, s1 = 0, s2 = 0, s3 = 0;
        for (int j = 0; j < d; j++) {
            int2 md = __ldg(&vm[j]);
            int zc0 = z + md.y; if (zc0 >= ZL) zc0 -= ZL;
            int a0 = zc0 & ~3;
            int a1 = a0 + 4; if (a1 >= ZL) a1 = 0;
            unsigned w0 = *(const unsigned*)(c2vb + md.x + a0);
            unsigned w1 = *(const unsigned*)(c2vb + md.x + a1);
            unsigned v  = __funnelshift_r(w0, w1, (zc0 & 3) * 8);
            s0 += (int)(v << 24) >> 24;
            s1 += (int)(v << 16) >> 24;
            s2 += (int)(v <<  8) >> 24;
            s3 += (int)v >> 24;
        }
        float4 xv = *(const float4*)(xab + n * ZL + z);
        float4 r;
        r.x = 0.5f * (float)s0 + xv.x;
        r.y = 0.5f * (float)s1 + xv.y;
        r.z = 0.5f * (float)s2 + xv.z;
        r.w = 0.5f * (float)s3 + xv.w;
        if (write_tot) *(float4*)(totb + n * ZL + z) = r;
        tile[n][zl + 0] = r.x;
        tile[n][zl + 1] = r.y;
        tile[n][zl + 2] = r.z;
        tile[n][zl + 3] = r.w;
    }
    __syncthreads();

    // out[b][z0+zz][n] = tile[n][zz]; consecutive threads -> consecutive n
    float* __restrict__ ob = out + ((size_t)b * ZL + z0) * NV;
    for (int i = threadIdx.x; i < VZC * NV; i += 256) {
        int zz = i / NV, n = i - zz * NV;
        ob[(size_t)zz * NV + n] = tile[n][zz];
    }
}

// ---------------- launch -------------------------------------------------
extern "C" void kernel_launch(void* const* d_in, const int* in_sizes, int n_in,
                              void* d_out, int out_size)
{
    const float* xa   = (const float*)d_in[0];  // [B][N][Z]
    const float* cnw  = (const float*)d_in[1];  // [NITERS]
    const int*   evn  = (const int*)  d_in[2];  // [E]
    const int*   ecn  = (const int*)  d_in[3];  // [E]
    const int*   esh  = (const int*)  d_in[4];  // [E]
    float*       out  = (float*)d_out;          // [NITERS][B][Z][N]

    setup_kernel<<<1, 384>>>(ecn, evn, esh);

    const size_t slab = (size_t)BATCH * ZL * NV;
    dim3 cn_grid(MC, BATCH / 4);
    dim3 vn_grid(ZL / VZC, BATCH);

    for (int it = 0; it < NITERS; it++) {
        if (it == 0) cn_kernel<true ><<<cn_grid, 384>>>(xa, cnw, it);
        else         cn_kernel<false><<<cn_grid, 384>>>(xa, cnw, it);
        vn_kernel<<<vn_grid, 256>>>(xa, out + (size_t)it * slab,
                                    it == NITERS - 1 ? 0 : 1);
    }
}